// round 16
// baseline (speedup 1.0000x reference)
#include <cuda_runtime.h>
#include <cuda_bf16.h>
#include <cstdint>

// ---------------- constants ----------------
#define T_LEN (1 << 21)          // 2,097,152
#define B_CH  8192               // chains (256 steps each)
#define NPRE  2048               // k_pre blocks
#define NREF  32                 // refine blocks (4096 threads, 2 chains/thread)
#define HALF_CH 4096
#define S_EQS (166.0f / 350.0f)  // stationary init in sigma units

// ---------------- device scratch ----------------
// packed quads: 4 consecutive steps of one chain per float4.
// float4 index: ((C>>5)<<11) + ((i>>2)<<5) + (C&31)
__device__ float4 g_t4[(T_LEN / 4) + 1024];  // ts = tanh(d/350) quads (ALL passes)
__device__ float  g_send[2][B_CH];           // ping-pong block end states (sigma)
__device__ float  g_ck[16][B_CH];            // 16-step checkpoints (sigma)
__device__ float  g_prepart[NPRE * 4];       // Σpn, Σpn², Σen, Σen²
__device__ float  g_spart[NREF * 4];         // Σps, Σps², Σpc, Σpc² (rescaled)
__device__ float  g_stats[8];                // mu[4], inv_sigma[4]
__device__ int    g_done;                    // stats-finalize ticket (reset each use)

// ---------------- f32x2 packed helpers ----------------
__device__ __forceinline__ uint64_t pk2(float a, float b) {
    uint64_t r; asm("mov.b64 %0, {%1, %2};" : "=l"(r) : "f"(a), "f"(b)); return r;
}
__device__ __forceinline__ void upk2(float& a, float& b, uint64_t v) {
    asm("mov.b64 {%0, %1}, %2;" : "=f"(a), "=f"(b) : "l"(v));
}
#define F2FMA(d, a, b, c) asm("fma.rn.f32x2 %0, %1, %2, %3;" : "=l"(d) : "l"(a), "l"(b), "l"(c))
#define F2MUL(d, a, b)    asm("mul.rn.f32x2 %0, %1, %2;"     : "=l"(d) : "l"(a), "l"(b))

// perc-poly constants
#define K9f (4.0f / 9.0f)
#define KQf (K9f * K9f * K9f * K9f)
#define A1f (-0.25f * KQf)
#define A2f (0.15625f * KQf * KQf)

// ---------------- signed tanh (d-only) ----------------
__device__ __forceinline__ float tanh_s(float d) {
    const float INV = 1.0f / 350.0f;
    float m = d * INV;                                  // |m| <= 0.0286
    return m * fmaf(m * m, -0.33333333f, 1.0f);        // odd series, rel err ~9e-8
}

// ---------------- scalar step (k_out), same op ordering as packed path -----------
__device__ __forceinline__ float grs_s(float sg, float ts, float& ps_o, float& pc_o) {
    float alpha = fmaxf(-ts, 0.0f);
    float G     = fmaxf(ts, 0.0f);
    float Dpa   = fminf(ts + ts, 0.0f) + alpha;
    float c     = fmaf(ts, sg, alpha);
    float omc   = fmaf(c, -1.0f, 1.0f);
    float cc    = c * c;
    float inner = fmaf(c, -1.0f, Dpa);
    float h     = fmaf(cc, omc, omc);                  // 1/(1+c)+O(c^4)
    float z     = fmaf(sg, inner, G);
    float s1    = fmaf(z, h, sg);
    float s1s   = s1 * s1;
    float v     = s1s * s1s;
    float P     = fmaf(v, A2f, A1f);
    float s1v   = s1 * v;
    float s2    = fmaf(s1v, P, s1);
    ps_o = fmaxf(s1 - sg, 0.0f);
    pc_o = s1 - s2;
    return s2;
}

// ---------------- prologue: d = P-E, ts quads (packed transpose), pn/en stats -----
__global__ void __launch_bounds__(256) k_pre(const float2* __restrict__ x) {
    __shared__ float tile[32][33];
    __shared__ float red[4][256];
    int bid = blockIdx.x;
    int c0  = (bid >> 3) << 5;       // 32-chain group base
    int i0  = (bid & 7) << 5;        // 32-step tile base
    int tid = threadIdx.x;
    float a0 = 0.f, a1 = 0.f, a2 = 0.f, a3 = 0.f;
#pragma unroll
    for (int k = 0; k < 4; k++) {
        int e  = tid + (k << 8);
        int cc = e >> 5, ii = e & 31;
        float2 v = x[(c0 + cc) * 256 + i0 + ii];          // coalesced
        float d  = v.x - v.y;
        float pn = fmaxf(d, 0.0f);
        float en = fmaxf(-d, 0.0f);
        tile[cc][ii] = tanh_s(d);
        a0 += pn; a1 = fmaf(pn, pn, a1);
        a2 += en; a3 = fmaf(en, en, a3);
    }
    __syncthreads();
    {   // packed quad write: thread -> (chain cc, quad qq)
        int cc = tid & 31, qq = tid >> 5;                 // qq in 0..7
        float4 v4 = make_float4(tile[cc][qq * 4 + 0], tile[cc][qq * 4 + 1],
                                tile[cc][qq * 4 + 2], tile[cc][qq * 4 + 3]);
        g_t4[((c0 >> 5) << 11) + (((i0 >> 2) + qq) << 5) + cc] = v4;  // coalesced 512B
    }
    red[0][tid] = a0; red[1][tid] = a1; red[2][tid] = a2; red[3][tid] = a3;
    __syncthreads();
    for (int o = 128; o > 0; o >>= 1) {
        if (tid < o) {
            red[0][tid] += red[0][tid + o]; red[1][tid] += red[1][tid + o];
            red[2][tid] += red[2][tid + o]; red[3][tid] += red[3][tid + o];
        }
        __syncthreads();
    }
    if (tid < 4) g_prepart[bid * 4 + tid] = red[tid][0];
}

// ---------------- refine pass: 2 chains/thread via packed f32x2 ----------------
template <int FIRST, int STATS>
__global__ void __launch_bounds__(128) k_refine(int srcIdx, int dstIdx) {
    int t  = blockIdx.x * 128 + threadIdx.x;   // 0..4095
    int Ca = t;
    int Cb = t + HALF_CH;
    const float4* pa = g_t4 + ((Ca >> 5) << 11) + (Ca & 31);
    const float4* pb = g_t4 + ((Cb >> 5) << 11) + (Cb & 31);
    float sga = (Ca == 0) ? 0.0f : (FIRST ? S_EQS : g_send[srcIdx][Ca - 1]);
    float sgb = FIRST ? S_EQS : g_send[srcIdx][Cb - 1];
    uint64_t sg2 = pk2(sga, sgb);
    const uint64_t M1_2  = pk2(-1.0f, -1.0f);
    const uint64_t ONE_2 = pk2(1.0f, 1.0f);
    const uint64_t A1_2  = pk2(A1f, A1f);
    const uint64_t A2_2  = pk2(A2f, A2f);
    float q0a = 0.f, q1a = 0.f, q2a = 0.f, q3a = 0.f;
    float q0b = 0.f, q1b = 0.f, q2b = 0.f, q3b = 0.f;
    if (STATS) { g_ck[0][Ca] = sga; g_ck[0][Cb] = sgb; }
    float4 QAa[4], QAb[4], QBa[4], QBb[4];
#pragma unroll
    for (int k = 0; k < 4; k++) { QAa[k] = __ldg(&pa[k << 5]);       QAb[k] = __ldg(&pb[k << 5]); }
#pragma unroll
    for (int k = 0; k < 4; k++) { QBa[k] = __ldg(&pa[(4 + k) << 5]); QBb[k] = __ldg(&pb[(4 + k) << 5]); }
#pragma unroll 1
    for (int i0 = 0; i0 < 256; i0 += 32) {
        float tsa[16], tsb[16];
#pragma unroll
        for (int k = 0; k < 4; k++) {
            tsa[4*k+0] = QAa[k].x; tsa[4*k+1] = QAa[k].y; tsa[4*k+2] = QAa[k].z; tsa[4*k+3] = QAa[k].w;
            tsb[4*k+0] = QAb[k].x; tsb[4*k+1] = QAb[k].y; tsb[4*k+2] = QAb[k].z; tsb[4*k+3] = QAb[k].w;
        }
#pragma unroll
        for (int k = 0; k < 4; k++) {
            QAa[k] = __ldg(&pa[((i0 >> 2) + 8 + k) << 5]);   // pad absorbs overrun
            QAb[k] = __ldg(&pb[((i0 >> 2) + 8 + k) << 5]);
        }
#pragma unroll
        for (int j = 0; j < 16; j++) {
            float ta = tsa[j], tb = tsb[j];
            float ala = fmaxf(-ta, 0.0f), alb = fmaxf(-tb, 0.0f);      // ALU
            float Gaa = fmaxf(ta, 0.0f),  Gbb = fmaxf(tb, 0.0f);       // ALU
            float Dpaa = fminf(ta + ta, 0.0f) + ala;
            float Dpab = fminf(tb + tb, 0.0f) + alb;
            uint64_t ts2 = pk2(ta, tb), al2 = pk2(ala, alb);
            uint64_t G2 = pk2(Gaa, Gbb), Dp2 = pk2(Dpaa, Dpab);
            uint64_t c2, omc2, cc2, in2, h2, z2, s1_2, s1s2, v2, P2, s1v2, s2_2;
            F2FMA(c2, ts2, sg2, al2);
            F2FMA(omc2, c2, M1_2, ONE_2);
            F2MUL(cc2, c2, c2);
            F2FMA(in2, c2, M1_2, Dp2);
            F2FMA(h2, cc2, omc2, omc2);
            F2FMA(z2, sg2, in2, G2);
            F2FMA(s1_2, z2, h2, sg2);
            F2MUL(s1s2, s1_2, s1_2);
            F2MUL(v2, s1s2, s1s2);
            F2FMA(P2, v2, A2_2, A1_2);
            F2MUL(s1v2, s1_2, v2);
            F2FMA(s2_2, s1v2, P2, s1_2);
            if (STATS) {
                float s1a, s1b, s2a, s2b, ga, gb;
                upk2(s1a, s1b, s1_2); upk2(s2a, s2b, s2_2); upk2(ga, gb, sg2);
                float psa = fmaxf(s1a - ga, 0.0f), psb = fmaxf(s1b - gb, 0.0f);
                float pca = s1a - s2a, pcb = s1b - s2b;
                q0a += psa; q1a = fmaf(psa, psa, q1a); q2a += pca; q3a = fmaf(pca, pca, q3a);
                q0b += psb; q1b = fmaf(psb, psb, q1b); q2b += pcb; q3b = fmaf(pcb, pcb, q3b);
            }
            sg2 = s2_2;
        }
        if (STATS) {   // checkpoint at step i0+16
            float ga, gb; upk2(ga, gb, sg2);
            g_ck[(i0 >> 4) + 1][Ca] = ga; g_ck[(i0 >> 4) + 1][Cb] = gb;
        }
#pragma unroll
        for (int k = 0; k < 4; k++) {
            tsa[4*k+0] = QBa[k].x; tsa[4*k+1] = QBa[k].y; tsa[4*k+2] = QBa[k].z; tsa[4*k+3] = QBa[k].w;
            tsb[4*k+0] = QBb[k].x; tsb[4*k+1] = QBb[k].y; tsb[4*k+2] = QBb[k].z; tsb[4*k+3] = QBb[k].w;
        }
#pragma unroll
        for (int k = 0; k < 4; k++) {
            QBa[k] = __ldg(&pa[((i0 >> 2) + 12 + k) << 5]);
            QBb[k] = __ldg(&pb[((i0 >> 2) + 12 + k) << 5]);
        }
#pragma unroll
        for (int j = 0; j < 16; j++) {
            float ta = tsa[j], tb = tsb[j];
            float ala = fmaxf(-ta, 0.0f), alb = fmaxf(-tb, 0.0f);
            float Gaa = fmaxf(ta, 0.0f),  Gbb = fmaxf(tb, 0.0f);
            float Dpaa = fminf(ta + ta, 0.0f) + ala;
            float Dpab = fminf(tb + tb, 0.0f) + alb;
            uint64_t ts2 = pk2(ta, tb), al2 = pk2(ala, alb);
            uint64_t G2 = pk2(Gaa, Gbb), Dp2 = pk2(Dpaa, Dpab);
            uint64_t c2, omc2, cc2, in2, h2, z2, s1_2, s1s2, v2, P2, s1v2, s2_2;
            F2FMA(c2, ts2, sg2, al2);
            F2FMA(omc2, c2, M1_2, ONE_2);
            F2MUL(cc2, c2, c2);
            F2FMA(in2, c2, M1_2, Dp2);
            F2FMA(h2, cc2, omc2, omc2);
            F2FMA(z2, sg2, in2, G2);
            F2FMA(s1_2, z2, h2, sg2);
            F2MUL(s1s2, s1_2, s1_2);
            F2MUL(v2, s1s2, s1s2);
            F2FMA(P2, v2, A2_2, A1_2);
            F2MUL(s1v2, s1_2, v2);
            F2FMA(s2_2, s1v2, P2, s1_2);
            if (STATS) {
                float s1a, s1b, s2a, s2b, ga, gb;
                upk2(s1a, s1b, s1_2); upk2(s2a, s2b, s2_2); upk2(ga, gb, sg2);
                float psa = fmaxf(s1a - ga, 0.0f), psb = fmaxf(s1b - gb, 0.0f);
                float pca = s1a - s2a, pcb = s1b - s2b;
                q0a += psa; q1a = fmaf(psa, psa, q1a); q2a += pca; q3a = fmaf(pca, pca, q3a);
                q0b += psb; q1b = fmaf(psb, psb, q1b); q2b += pcb; q3b = fmaf(pcb, pcb, q3b);
            }
            sg2 = s2_2;
        }
        if (STATS) {
            int nx = i0 + 32;
            if (nx < 256) {
                float ga, gb; upk2(ga, gb, sg2);
                g_ck[nx >> 4][Ca] = ga; g_ck[nx >> 4][Cb] = gb;
            }
        }
    }
    float sgaF, sgbF; upk2(sgaF, sgbF, sg2);
    if (!STATS) { g_send[dstIdx][Ca] = sgaF; g_send[dstIdx][Cb] = sgbF; }
    if (STATS) {
        float q0 = q0a + q0b, q1 = q1a + q1b, q2 = q2a + q2b, q3 = q3a + q3b;
        q0 *= 350.0f; q1 *= 122500.0f; q2 *= 350.0f; q3 *= 122500.0f;
        __shared__ float rd[4][128];
        __shared__ int lastf;
        int tx = threadIdx.x;
        rd[0][tx] = q0; rd[1][tx] = q1; rd[2][tx] = q2; rd[3][tx] = q3;
        __syncthreads();
        for (int o = 64; o > 0; o >>= 1) {
            if (tx < o) {
                rd[0][tx] += rd[0][tx + o]; rd[1][tx] += rd[1][tx + o];
                rd[2][tx] += rd[2][tx + o]; rd[3][tx] += rd[3][tx + o];
            }
            __syncthreads();
        }
        if (tx < 4) g_spart[blockIdx.x * 4 + tx] = rd[tx][0];
        __threadfence();
        if (tx == 0) lastf = (atomicAdd(&g_done, 1) == NREF - 1);
        __syncthreads();
        if (lastf) {   // last-arriving block finalizes mu / inv_sigma
            __threadfence();
            __shared__ float sd[8][128];
            float acc[8] = {0, 0, 0, 0, 0, 0, 0, 0};
            for (int b = tx; b < NPRE; b += 128) {
                acc[0] += g_prepart[b * 4 + 0]; acc[1] += g_prepart[b * 4 + 1];
                acc[2] += g_prepart[b * 4 + 2]; acc[3] += g_prepart[b * 4 + 3];
            }
            if (tx < NREF) {
                acc[4] = g_spart[tx * 4 + 0]; acc[5] = g_spart[tx * 4 + 1];
                acc[6] = g_spart[tx * 4 + 2]; acc[7] = g_spart[tx * 4 + 3];
            }
#pragma unroll
            for (int k = 0; k < 8; k++) sd[k][tx] = acc[k];
            __syncthreads();
            for (int o = 64; o > 0; o >>= 1) {
                if (tx < o) {
#pragma unroll
                    for (int k = 0; k < 8; k++) sd[k][tx] += sd[k][tx + o];
                }
                __syncthreads();
            }
            if (tx == 0) {
                const float invT = 1.0f / (float)T_LEN;
                float S[4]  = {sd[0][0], sd[2][0], sd[4][0], sd[6][0]};
                float S2[4] = {sd[1][0], sd[3][0], sd[5][0], sd[7][0]};
#pragma unroll
                for (int k = 0; k < 4; k++) {
                    float mu  = S[k] * invT;
                    float var = fmaxf(S2[k] * invT - mu * mu, 0.0f);
                    g_stats[k]     = mu;
                    g_stats[4 + k] = 1.0f / sqrtf(var);
                }
                g_done = 0;     // reset ticket for next graph replay
            }
        }
    }
}

// ---------------- output pass: 16 steps/warp from checkpoints ----------------
__global__ void __launch_bounds__(64) k_out(float4* __restrict__ out, float* __restrict__ ss) {
    __shared__ float4 tout[32][33];
    __shared__ float  tss[32][33];
    int tid  = threadIdx.x;
    int lane = tid & 31;
    int wp   = tid >> 5;             // warp 0/1
    int cg   = blockIdx.x >> 3;      // chain group (32 chains)
    int b    = blockIdx.x & 7;       // 32-step tile index
    int w    = (b << 1) + wp;        // 16-step window index (0..15)
    int C    = (cg << 5) + lane;
    const float4* pq = g_t4 + (cg << 11) + lane;
    float sg = g_ck[w][C];
    // normalization constants: pn/en carry 350x (reconstructed m units), ps/pc/ss too
    float c0 = 350.0f * g_stats[4], o0 = g_stats[0] * g_stats[4];
    float c1 = 350.0f * g_stats[5], o1 = g_stats[1] * g_stats[5];
    float c2 = 350.0f * g_stats[6], o2 = g_stats[2] * g_stats[6];
    float c3 = 350.0f * g_stats[7], o3 = g_stats[3] * g_stats[7];
    float4 Qt[4];
#pragma unroll
    for (int k = 0; k < 4; k++) Qt[k] = __ldg(&pq[((w << 2) + k) << 5]);
    int colbase = wp << 4;           // this warp's 16 columns within the 32-step tile
#pragma unroll
    for (int q = 0; q < 4; q++) {
        float tv[4] = {Qt[q].x, Qt[q].y, Qt[q].z, Qt[q].w};
#pragma unroll
        for (int j = 0; j < 4; j++) {
            float ts = tv[j];
            // invert tanh series: m = ts + ts^3/3  (rel err ~2e-7);  pn/en = 350*max(+/-m,0)
            float t2 = ts * ts;
            float m  = fmaf(t2 * ts, 0.33333333f, ts);
            float pn = fmaxf(m, 0.0f);
            float en = fmaxf(-m, 0.0f);
            float ps, pc;
            sg = grs_s(sg, ts, ps, pc);
            tout[lane][colbase + q * 4 + j] = make_float4(fmaf(pn, c0, -o0),
                                                          fmaf(en, c1, -o1),
                                                          fmaf(ps, c2, -o2),
                                                          fmaf(pc, c3, -o3));
            tss[lane][colbase + q * 4 + j] = 350.0f * sg;
        }
    }
    __syncthreads();
    int rowstart = (cg << 13) + (b << 5);
#pragma unroll 1
    for (int e = tid; e < 1024; e += 64) {
        int j = e >> 5, i = e & 31;
        out[rowstart + j * 256 + i] = tout[j][i];    // 512B coalesced per warp
        ss [rowstart + j * 256 + i] = tss[j][i];     // 128B coalesced per warp
    }
}

// ---------------- launch ----------------
extern "C" void kernel_launch(void* const* d_in, const int* in_sizes, int n_in,
                              void* d_out, int out_size) {
    (void)in_sizes; (void)n_in; (void)out_size;
    const float2* x = (const float2*)d_in[0];
    float* out = (float*)d_out;                  // (T,4) normalized
    float* ssp = out + 4 * (size_t)T_LEN;        // (T,1) state trace

    k_pre<<<NPRE, 256>>>(x);
    k_refine<1, 0><<<NREF, 128>>>(0, 0);   // init at sigma*, history 256
    k_refine<0, 0><<<NREF, 128>>>(0, 1);   // history 512
    k_refine<0, 1><<<NREF, 128>>>(1, 0);   // stats + 16-step ck + fused finalize
    k_out<<<8 * (B_CH / 32), 64>>>((float4*)out, ssp);
}